// round 15
// baseline (speedup 1.0000x reference)
#include <cuda_runtime.h>
#include <cuda_bf16.h>
#include <cstdint>

// Problem constants
#define BATCH   8192
#define R_DIM   8
#define PH_DIM  16
#define PAIRS   1024
#define OUT_U   8192   // PAIRS * R

#define PK_NCHUNK 32         // 32 pair chunks of 32 pairs
#define MK_TILE   32
#define MK_NTILE  (BATCH / MK_TILE)   // 256
#define N_SLICES  (PK_NCHUNK + 2)     // 34
#define ARRIVALS  48                  // 32 pair CTAs + 16 mlp CTAs per 256-sample tile

typedef unsigned long long ull;

// Deterministic partial buffer: 32 interaction chunks + X + Z
__device__ float g_partial[N_SLICES * BATCH];
// Transposed inputs: [32][8192]
__device__ float g_xT[32 * BATCH];
__device__ float g_zT[32 * BATCH];
// Per-256-sample-tile arrival counters (zero-init; reducer resets -> replay-safe)
__device__ int g_cnt[32];

// ---- packed f32x2 helpers ---------------------------------------------------
__device__ __forceinline__ ull pack2(float lo, float hi) {
    ull r;
    asm("mov.b64 %0, {%1, %2};" : "=l"(r) : "f"(lo), "f"(hi));
    return r;
}
__device__ __forceinline__ void unpack2(ull v, float& lo, float& hi) {
    asm("mov.b64 {%0, %1}, %2;" : "=f"(lo), "=f"(hi) : "l"(v));
}
__device__ __forceinline__ ull fma2(ull a, ull b, ull c) {
    ull d;
    asm("fma.rn.f32x2 %0, %1, %2, %3;" : "=l"(d) : "l"(a), "l"(b), "l"(c));
    return d;
}
__device__ __forceinline__ uint32_t tf32_rna(float v) {
    uint32_t u;
    asm("cvt.rna.tf32.f32 %0, %1;" : "=r"(u) : "f"(v));
    return u;
}
// mma.sync m16n8k8 tf32: D = A(16x8,row) * B(8x8,col) + C  (fp32 accum)
__device__ __forceinline__ void mma_tf32(float& d0, float& d1, float& d2, float& d3,
                                         uint32_t a0, uint32_t a1, uint32_t a2, uint32_t a3,
                                         uint32_t b0, uint32_t b1) {
    asm volatile(
        "mma.sync.aligned.m16n8k8.row.col.f32.tf32.tf32.f32 "
        "{%0,%1,%2,%3}, {%4,%5,%6,%7}, {%8,%9}, {%0,%1,%2,%3};\n"
        : "+f"(d0), "+f"(d1), "+f"(d2), "+f"(d3)
        : "r"(a0), "r"(a1), "r"(a2), "r"(a3), "r"(b0), "r"(b1));
}

// Fixed ascending per-sample reduction chain — IDENTICAL in both kernels so the
// output is bit-identical no matter which CTA performs it.
__device__ __forceinline__ float reduce_sample(int smp) {
    float s = 0.0f;
    #pragma unroll
    for (int c = 0; c < N_SLICES; ++c)
        s += g_partial[c * BATCH + smp];
    return s;
}

// ---------------------------------------------------------------------------
// Kernel 0: transpose x,z [8192][32] -> [32][8192]
// ---------------------------------------------------------------------------
__global__ __launch_bounds__(256)
void transpose_kernel(const float* __restrict__ x, const float* __restrict__ z)
{
    __shared__ float tx[64 * 33];
    __shared__ float tz[64 * 33];
    const int tid = threadIdx.x;
    const int g0  = blockIdx.x * 64;

    for (int idx = tid; idx < 64 * 32; idx += 256) {
        int s = idx >> 5, c = idx & 31;
        tx[s * 33 + c] = x[(size_t)g0 * 32 + idx];
        tz[s * 33 + c] = z[(size_t)g0 * 32 + idx];
    }
    __syncthreads();
    for (int idx = tid; idx < 64 * 32; idx += 256) {
        int c = idx >> 6, s = idx & 63;
        g_xT[(size_t)c * BATCH + g0 + s] = tx[s * 33 + c];
        g_zT[(size_t)c * BATCH + g0 + s] = tz[s * 33 + c];
    }
}

// ---------------------------------------------------------------------------
// Kernel 1: main-effect MLPs (32->128->64->1). blockIdx.y = part (x or z).
// MK_TILE=32: 512 CTAs (x2 parts in grid.y), 62KB smem -> ~24 warps/SM.
// ---------------------------------------------------------------------------
__global__ __launch_bounds__(256)
void mlp_kernel(float* __restrict__ out,
                const float* __restrict__ x, const float* __restrict__ z,
                const float* __restrict__ xw1, const float* __restrict__ xb1,
                const float* __restrict__ xw2, const float* __restrict__ xb2,
                const float* __restrict__ xw3, const float* __restrict__ xb3,
                const float* __restrict__ zw1, const float* __restrict__ zb1,
                const float* __restrict__ zw2, const float* __restrict__ zb2,
                const float* __restrict__ zw3, const float* __restrict__ zb3)
{
    extern __shared__ float sm[];
    float* in_sm = sm;                 // 32*32   = 1024
    float* h1_sm = sm + 1024;          // 32*128  = 4096
    float* w2_sm = sm + 5120;          // 128*64  = 8192
    float* h2_sm = sm + 13312;         // 32*68   = 2176
    float* w3_sm = sm + 15488;         // 64   (total 15552 floats = 62208 B)

    const int tid  = threadIdx.x;
    const int tile = blockIdx.x;
    const int part = blockIdx.y;
    const int g0   = tile * MK_TILE;

    const float* in = part ? z   : x;
    const float* w1 = part ? zw1 : xw1;
    const float* b1 = part ? zb1 : xb1;
    const float* w2 = part ? zw2 : xw2;
    const float* b2 = part ? zb2 : xb2;
    const float* w3 = part ? zw3 : xw3;
    const float* b3 = part ? zb3 : xb3;

    for (int idx = tid; idx < MK_TILE * 32; idx += 256)
        in_sm[idx] = in[(size_t)g0 * 32 + idx];
    for (int idx = tid; idx < 128 * 64; idx += 256)
        w2_sm[idx] = w2[idx];
    if (tid < 64) w3_sm[tid] = w3[tid];

    const int u    = tid & 127;        // hidden unit
    const int half = tid >> 7;         // sample half (0/1)

    float wc[32];
    #pragma unroll
    for (int l = 0; l < 32; ++l) wc[l] = w1[l * 128 + u];
    const float bc = b1[u];

    __syncthreads();

    // ---- phase 1: 4 samples in flight, 16 samples per half ----
    for (int s0 = half * 16; s0 < half * 16 + 16; s0 += 4) {
        float a0 = bc, a1 = bc, a2 = bc, a3 = bc;
        const float4* r0 = (const float4*)(in_sm + (s0 + 0) * 32);
        const float4* r1 = (const float4*)(in_sm + (s0 + 1) * 32);
        const float4* r2 = (const float4*)(in_sm + (s0 + 2) * 32);
        const float4* r3 = (const float4*)(in_sm + (s0 + 3) * 32);
        #pragma unroll
        for (int l4 = 0; l4 < 8; ++l4) {
            float4 v0 = r0[l4], v1 = r1[l4], v2 = r2[l4], v3 = r3[l4];
            float w0 = wc[l4 * 4 + 0], w1c = wc[l4 * 4 + 1];
            float w2c = wc[l4 * 4 + 2], w3c = wc[l4 * 4 + 3];
            a0 = fmaf(v0.x, w0, a0); a1 = fmaf(v1.x, w0, a1);
            a2 = fmaf(v2.x, w0, a2); a3 = fmaf(v3.x, w0, a3);
            a0 = fmaf(v0.y, w1c, a0); a1 = fmaf(v1.y, w1c, a1);
            a2 = fmaf(v2.y, w1c, a2); a3 = fmaf(v3.y, w1c, a3);
            a0 = fmaf(v0.z, w2c, a0); a1 = fmaf(v1.z, w2c, a1);
            a2 = fmaf(v2.z, w2c, a2); a3 = fmaf(v3.z, w2c, a3);
            a0 = fmaf(v0.w, w3c, a0); a1 = fmaf(v1.w, w3c, a1);
            a2 = fmaf(v2.w, w3c, a2); a3 = fmaf(v3.w, w3c, a3);
        }
        h1_sm[(s0 + 0) * 128 + u] = fmaxf(a0, 0.0f);
        h1_sm[(s0 + 1) * 128 + u] = fmaxf(a1, 0.0f);
        h1_sm[(s0 + 2) * 128 + u] = fmaxf(a2, 0.0f);
        h1_sm[(s0 + 3) * 128 + u] = fmaxf(a3, 0.0f);
    }
    __syncthreads();

    // ---- phase 2: 2 samples/thread, f32x2 ----
    {
        const int oq = tid & 15;
        const int sg = tid >> 4;           // 16 groups x 2 samples
        float4 bb = ((const float4*)b2)[oq];
        ull accA[2], accB[2];
        const ull bA = pack2(bb.x, bb.y);
        const ull bB = pack2(bb.z, bb.w);
        #pragma unroll
        for (int ss = 0; ss < 2; ++ss) { accA[ss] = bA; accB[ss] = bB; }

        const float4* w24   = (const float4*)w2_sm;
        const float4* hbase = (const float4*)(h1_sm + sg * 2 * 128);

        #pragma unroll 4
        for (int l4 = 0; l4 < 32; ++l4) {
            float4 wA = w24[(l4 * 4 + 0) * 16 + oq];
            float4 wB = w24[(l4 * 4 + 1) * 16 + oq];
            float4 wC = w24[(l4 * 4 + 2) * 16 + oq];
            float4 wD = w24[(l4 * 4 + 3) * 16 + oq];
            const ulonglong2 wAp = *(const ulonglong2*)&wA;
            const ulonglong2 wBp = *(const ulonglong2*)&wB;
            const ulonglong2 wCp = *(const ulonglong2*)&wC;
            const ulonglong2 wDp = *(const ulonglong2*)&wD;
            #pragma unroll
            for (int ss = 0; ss < 2; ++ss) {
                float4 hv = hbase[ss * 32 + l4];
                ull hx = pack2(hv.x, hv.x);
                ull hy = pack2(hv.y, hv.y);
                ull hz = pack2(hv.z, hv.z);
                ull hw = pack2(hv.w, hv.w);
                accA[ss] = fma2(hx, wAp.x, accA[ss]); accB[ss] = fma2(hx, wAp.y, accB[ss]);
                accA[ss] = fma2(hy, wBp.x, accA[ss]); accB[ss] = fma2(hy, wBp.y, accB[ss]);
                accA[ss] = fma2(hz, wCp.x, accA[ss]); accB[ss] = fma2(hz, wCp.y, accB[ss]);
                accA[ss] = fma2(hw, wDp.x, accA[ss]); accB[ss] = fma2(hw, wDp.y, accB[ss]);
            }
        }
        #pragma unroll
        for (int ss = 0; ss < 2; ++ss) {
            const int s = sg * 2 + ss;
            float a0, a1, a2, a3;
            unpack2(accA[ss], a0, a1);
            unpack2(accB[ss], a2, a3);
            float4 r;
            r.x = fmaxf(a0, 0.0f); r.y = fmaxf(a1, 0.0f);
            r.z = fmaxf(a2, 0.0f); r.w = fmaxf(a3, 0.0f);
            *(float4*)(h2_sm + s * 68 + oq * 4) = r;
        }
    }
    __syncthreads();

    // ---- phase 3: 8 threads per sample + 3-level shfl ----
    {
        const int s = tid >> 3, q = tid & 7;
        const float4* hr = (const float4*)(h2_sm + s * 68 + q * 8);
        const float4* wr = (const float4*)(w3_sm + q * 8);
        float acc = 0.0f;
        #pragma unroll
        for (int i = 0; i < 2; ++i) {
            float4 h = hr[i], w = wr[i];
            acc = fmaf(h.x, w.x, acc);
            acc = fmaf(h.y, w.y, acc);
            acc = fmaf(h.z, w.z, acc);
            acc = fmaf(h.w, w.w, acc);
        }
        acc += __shfl_xor_sync(0xffffffffu, acc, 1);
        acc += __shfl_xor_sync(0xffffffffu, acc, 2);
        acc += __shfl_xor_sync(0xffffffffu, acc, 4);
        if (q == 0)
            g_partial[(PK_NCHUNK + part) * BATCH + g0 + s] = acc + b3[0];
    }

    // ---- arrival + (maybe) fused final reduction ----
    {
        __shared__ int last;
        const int pt = tile >> 3;            // 256-sample tile index
        __threadfence();
        __syncthreads();
        if (tid == 0)
            last = (atomicAdd(&g_cnt[pt], 1) == ARRIVALS - 1) ? 1 : 0;
        __syncthreads();
        if (last) {
            __threadfence();
            const int base = pt * 256;
            out[base + tid] = reduce_sample(base + tid);
            __syncthreads();
            if (tid == 0) g_cnt[pt] = 0;     // reset for next graph replay
        }
    }
}

// ---------------------------------------------------------------------------
// Kernel 2: structured interaction + per-pair MLPs via tf32 mma, pairs-outer.
// grid = (32 sample tiles of 256, 32 chunks) = 1024 CTAs, 128 threads.
// R9 loop body (proven best) + fused-reduction arrival epilogue.
// ---------------------------------------------------------------------------
__global__ __launch_bounds__(128, 6)
void pair_kernel(float* __restrict__ out,
                 const float* __restrict__ xzw, const float* __restrict__ xzb,
                 const float* __restrict__ pw1, const float* __restrict__ pb1,
                 const float* __restrict__ pw2)
{
    __shared__ __align__(16) ull   x2_sm[256];         // dup-packed x column (2KB)
    __shared__ __align__(16) float wq_sm[1024];        // [pair][c]{wx_c,wx_c4,wz_c,wz_c4,bb_c,bb_c4,0,0}
    __shared__ __align__(16) float bf_sm[4096];        // pw1 tf32 B-frags
    __shared__ __align__(16) float ep_sm[1024];        // [pair][cp]{pb,pb,pw2,pw2}

    const int tid   = threadIdx.x;
    const int tile  = blockIdx.x;    // 0..31
    const int chunk = blockIdx.y;    // 0..31
    const int g0    = tile * 256;
    const int p0    = chunk * 32;

    // ---- staging ----
    for (int idx = tid; idx < 256; idx += 128) {
        float xv = g_xT[(size_t)chunk * BATCH + g0 + idx];
        x2_sm[idx] = pack2(xv, xv);
    }
    for (int idx = tid; idx < 1024; idx += 128) {
        int pr = idx >> 5, c = (idx >> 3) & 3, e = idx & 7;
        int p  = p0 + pr;
        int j  = c + ((e & 1) << 2);
        float v = 0.f;
        if (e < 2)      v = xzw[(size_t)chunk * OUT_U + p * 8 + j];
        else if (e < 4) v = xzw[(size_t)(32 + pr) * OUT_U + p * 8 + j];
        else if (e < 6) v = xzb[p * 8 + j];
        wq_sm[idx] = v;
    }
    for (int idx = tid; idx < 4096; idx += 128) {
        int pr = idx >> 7, r = idx & 127;
        int nm = r >> 6, r2 = r & 63;
        int ln = r2 >> 1, half = r2 & 1;
        int k = (ln & 3) + (half << 2);
        int n = (ln >> 2) + (nm << 3);
        bf_sm[idx] = __uint_as_float(tf32_rna(pw1[(size_t)(p0 + pr) * 128 + k * 16 + n]));
    }
    for (int idx = tid; idx < 1024; idx += 128) {
        int pr = idx >> 5, r = idx & 31;
        int cp = r >> 2, e = r & 3;
        int col = 2 * cp + (e & 1);
        ep_sm[idx] = (e < 2) ? pb1[(p0 + pr) * 16 + col]
                             : pw2[(p0 + pr) * 16 + col];
    }
    __syncthreads();

    const int lane = tid & 31, w = tid >> 5;   // w 0..3
    const int g = lane >> 2, c = lane & 3;
    const int sbase = w * 64;                  // warp's sample base within tile

    float outv[8];
    #pragma unroll
    for (int i = 0; i < 8; ++i) outv[i] = 0.f;

    const float* zT = g_zT + g0;

    #pragma unroll 1
    for (int pl = 0; pl < 32; ++pl) {
        // per-pair registers (reused across 4 subtiles)
        ulonglong2 wu = *(const ulonglong2*)&wq_sm[(pl * 4 + c) * 8];
        ull bbu = *(const ull*)&wq_sm[(pl * 4 + c) * 8 + 4];
        uint2 bf0 = *(const uint2*)&bf_sm[pl * 128 + lane * 2];
        uint2 bf1 = *(const uint2*)&bf_sm[pl * 128 + 64 + lane * 2];
        float4 e0 = *(const float4*)&ep_sm[(pl * 8 + c) * 4];
        float4 e1 = *(const float4*)&ep_sm[(pl * 8 + c + 4) * 4];
        const float* zcol = zT + (size_t)pl * BATCH;

        #pragma unroll
        for (int sub = 0; sub < 4; ++sub) {
            const int srow = sbase + sub * 16 + g;
            float zg  = zcol[srow];
            float zg8 = zcol[srow + 8];

            // h in A-frag layout: rows {g, g+8} x cols {c, c+4}
            ull hg  = fma2(wu.x, x2_sm[srow],     fma2(wu.y, pack2(zg,  zg),  bbu));
            ull hg8 = fma2(wu.x, x2_sm[srow + 8], fma2(wu.y, pack2(zg8, zg8), bbu));
            float h0, h2, h1, h3;
            unpack2(hg,  h0, h2);
            unpack2(hg8, h1, h3);
            // raw fp32 bits: tf32 shares fp32 layout; MMA ignores low mantissa
            uint32_t a0 = __float_as_uint(fmaxf(h0, 0.f));
            uint32_t a1 = __float_as_uint(fmaxf(h1, 0.f));
            uint32_t a2 = __float_as_uint(fmaxf(h2, 0.f));
            uint32_t a3 = __float_as_uint(fmaxf(h3, 0.f));

            // t = h @ pw1 + pb1
            float d0 = e0.x, d1 = e0.y, d2 = e0.x, d3 = e0.y;
            mma_tf32(d0, d1, d2, d3, a0, a1, a2, a3, bf0.x, bf0.y);
            float f0 = e1.x, f1 = e1.y, f2 = e1.x, f3 = e1.y;
            mma_tf32(f0, f1, f2, f3, a0, a1, a2, a3, bf1.x, bf1.y);

            // out += relu(t) . pw2
            outv[2*sub]   = fmaf(fmaxf(d0, 0.f), e0.z, outv[2*sub]);
            outv[2*sub]   = fmaf(fmaxf(d1, 0.f), e0.w, outv[2*sub]);
            outv[2*sub]   = fmaf(fmaxf(f0, 0.f), e1.z, outv[2*sub]);
            outv[2*sub]   = fmaf(fmaxf(f1, 0.f), e1.w, outv[2*sub]);
            outv[2*sub+1] = fmaf(fmaxf(d2, 0.f), e0.z, outv[2*sub+1]);
            outv[2*sub+1] = fmaf(fmaxf(d3, 0.f), e0.w, outv[2*sub+1]);
            outv[2*sub+1] = fmaf(fmaxf(f2, 0.f), e1.z, outv[2*sub+1]);
            outv[2*sub+1] = fmaf(fmaxf(f3, 0.f), e1.w, outv[2*sub+1]);
        }
    }

    // reduce over the 4 col-partition threads of each row group
    #pragma unroll
    for (int i = 0; i < 8; ++i) {
        outv[i] += __shfl_xor_sync(0xffffffffu, outv[i], 1);
        outv[i] += __shfl_xor_sync(0xffffffffu, outv[i], 2);
    }
    if (c == 0) {
        #pragma unroll
        for (int sub = 0; sub < 4; ++sub) {
            g_partial[(size_t)chunk * BATCH + g0 + sbase + sub * 16 + g]     = outv[2*sub];
            g_partial[(size_t)chunk * BATCH + g0 + sbase + sub * 16 + g + 8] = outv[2*sub + 1];
        }
    }

    // ---- arrival + (maybe) fused final reduction ----
    {
        __shared__ int last;
        __threadfence();
        __syncthreads();
        if (tid == 0)
            last = (atomicAdd(&g_cnt[tile], 1) == ARRIVALS - 1) ? 1 : 0;
        __syncthreads();
        if (last) {
            __threadfence();
            for (int s = tid; s < 256; s += 128)
                out[g0 + s] = reduce_sample(g0 + s);
            __syncthreads();
            if (tid == 0) g_cnt[tile] = 0;   // reset for next graph replay
        }
    }
}

// ---------------------------------------------------------------------------
extern "C" void kernel_launch(void* const* d_in, const int* in_sizes, int n_in,
                              void* d_out, int out_size)
{
    const float* x   = (const float*)d_in[0];
    const float* z   = (const float*)d_in[1];
    const float* xw1 = (const float*)d_in[2];
    const float* xb1 = (const float*)d_in[3];
    const float* xw2 = (const float*)d_in[4];
    const float* xb2 = (const float*)d_in[5];
    const float* xw3 = (const float*)d_in[6];
    const float* xb3 = (const float*)d_in[7];
    const float* zw1 = (const float*)d_in[8];
    const float* zb1 = (const float*)d_in[9];
    const float* zw2 = (const float*)d_in[10];
    const float* zb2 = (const float*)d_in[11];
    const float* zw3 = (const float*)d_in[12];
    const float* zb3 = (const float*)d_in[13];
    const float* xzw = (const float*)d_in[14];
    const float* xzb = (const float*)d_in[15];
    const float* pw1 = (const float*)d_in[16];
    const float* pb1 = (const float*)d_in[17];
    const float* pw2 = (const float*)d_in[18];
    float* out = (float*)d_out;

    static cudaStream_t s2 = nullptr;
    static cudaEvent_t  e_fork = nullptr, e_join = nullptr;
    if (s2 == nullptr) {
        cudaStreamCreateWithFlags(&s2, cudaStreamNonBlocking);
        cudaEventCreateWithFlags(&e_fork, cudaEventDisableTiming);
        cudaEventCreateWithFlags(&e_join, cudaEventDisableTiming);
        cudaFuncSetAttribute(pair_kernel,
            cudaFuncAttributePreferredSharedMemoryCarveout, 100);
    }

    const size_t smem_mlp = 15552u * sizeof(float);   // 62208 B
    cudaFuncSetAttribute(mlp_kernel, cudaFuncAttributeMaxDynamicSharedMemorySize, (int)smem_mlp);

    // fork: mlp on side stream (its CTAs also feed the fused reduction)
    cudaEventRecord(e_fork, 0);
    cudaStreamWaitEvent(s2, e_fork, 0);
    mlp_kernel<<<dim3(MK_NTILE, 2), 256, smem_mlp, s2>>>(out, x, z,
        xw1, xb1, xw2, xb2, xw3, xb3,
        zw1, zb1, zw2, zb2, zw3, zb3);
    cudaEventRecord(e_join, s2);

    transpose_kernel<<<BATCH / 64, 256>>>(x, z);
    pair_kernel<<<dim3(32, 32), 128>>>(out, xzw, xzb, pw1, pb1, pw2);

    // join side stream so the captured graph's completion covers mlp's writes
    cudaStreamWaitEvent(0, e_join, 0);
}

// round 16
// speedup vs baseline: 1.0753x; 1.0753x over previous
#include <cuda_runtime.h>
#include <cuda_bf16.h>
#include <cstdint>

// Problem constants
#define BATCH   8192
#define R_DIM   8
#define PH_DIM  16
#define PAIRS   1024
#define OUT_U   8192   // PAIRS * R

#define PK_NCHUNK 32         // 32 pair chunks of 32 pairs
#define MK_TILE   64
#define MK_NTILE  (BATCH / MK_TILE)   // 128
#define N_SLICES  (PK_NCHUNK + 2)     // 34
#define ARRIVALS  40                  // 32 pair CTAs + 8 mlp CTAs per 256-sample tile

typedef unsigned long long ull;

// Deterministic partial buffer: 32 interaction chunks + X + Z
__device__ float g_partial[N_SLICES * BATCH];
// Transposed inputs: [32][8192]
__device__ float g_xT[32 * BATCH];
__device__ float g_zT[32 * BATCH];
// Per-256-sample-tile arrival counters (zero-init; reducer resets -> replay-safe)
__device__ int g_cnt[32];

// ---- packed f32x2 helpers ---------------------------------------------------
__device__ __forceinline__ ull pack2(float lo, float hi) {
    ull r;
    asm("mov.b64 %0, {%1, %2};" : "=l"(r) : "f"(lo), "f"(hi));
    return r;
}
__device__ __forceinline__ void unpack2(ull v, float& lo, float& hi) {
    asm("mov.b64 {%0, %1}, %2;" : "=f"(lo), "=f"(hi) : "l"(v));
}
__device__ __forceinline__ ull fma2(ull a, ull b, ull c) {
    ull d;
    asm("fma.rn.f32x2 %0, %1, %2, %3;" : "=l"(d) : "l"(a), "l"(b), "l"(c));
    return d;
}
__device__ __forceinline__ uint32_t tf32_rna(float v) {
    uint32_t u;
    asm("cvt.rna.tf32.f32 %0, %1;" : "=r"(u) : "f"(v));
    return u;
}
// mma.sync m16n8k8 tf32: D = A(16x8,row) * B(8x8,col) + C  (fp32 accum)
__device__ __forceinline__ void mma_tf32(float& d0, float& d1, float& d2, float& d3,
                                         uint32_t a0, uint32_t a1, uint32_t a2, uint32_t a3,
                                         uint32_t b0, uint32_t b1) {
    asm volatile(
        "mma.sync.aligned.m16n8k8.row.col.f32.tf32.tf32.f32 "
        "{%0,%1,%2,%3}, {%4,%5,%6,%7}, {%8,%9}, {%0,%1,%2,%3};\n"
        : "+f"(d0), "+f"(d1), "+f"(d2), "+f"(d3)
        : "r"(a0), "r"(a1), "r"(a2), "r"(a3), "r"(b0), "r"(b1));
}

// Fixed ascending per-sample reduction chain — IDENTICAL in both kernels so the
// output is bit-identical no matter which CTA performs it.
__device__ __forceinline__ float reduce_sample(int smp) {
    float s = 0.0f;
    #pragma unroll
    for (int c = 0; c < N_SLICES; ++c)
        s += g_partial[c * BATCH + smp];
    return s;
}

// ---------------------------------------------------------------------------
// Kernel 0: transpose x,z [8192][32] -> [32][8192]
// ---------------------------------------------------------------------------
__global__ __launch_bounds__(256)
void transpose_kernel(const float* __restrict__ x, const float* __restrict__ z)
{
    __shared__ float tx[64 * 33];
    __shared__ float tz[64 * 33];
    const int tid = threadIdx.x;
    const int g0  = blockIdx.x * 64;

    for (int idx = tid; idx < 64 * 32; idx += 256) {
        int s = idx >> 5, c = idx & 31;
        tx[s * 33 + c] = x[(size_t)g0 * 32 + idx];
        tz[s * 33 + c] = z[(size_t)g0 * 32 + idx];
    }
    __syncthreads();
    for (int idx = tid; idx < 64 * 32; idx += 256) {
        int c = idx >> 6, s = idx & 63;
        g_xT[(size_t)c * BATCH + g0 + s] = tx[s * 33 + c];
        g_zT[(size_t)c * BATCH + g0 + s] = tz[s * 33 + c];
    }
}

// ---------------------------------------------------------------------------
// Kernel 1: main-effect MLPs (32->128->64->1). blockIdx.y = part (x or z).
// MK_TILE=64, 256 threads. Phase 1 SIMT (R14), phase 2 via tf32 mma,
// phase 3 SIMT (R14). Fused-reduction arrival epilogue.
// smem layout (floats): in 0 | h1 2048 (64x132 padded) | w2f 10496 (B-frags)
//                       | h2 18688 (64x68) | w3 23040 | b2 23104 | total 23168
// ---------------------------------------------------------------------------
__global__ __launch_bounds__(256)
void mlp_kernel(float* __restrict__ out,
                const float* __restrict__ x, const float* __restrict__ z,
                const float* __restrict__ xw1, const float* __restrict__ xb1,
                const float* __restrict__ xw2, const float* __restrict__ xb2,
                const float* __restrict__ xw3, const float* __restrict__ xb3,
                const float* __restrict__ zw1, const float* __restrict__ zb1,
                const float* __restrict__ zw2, const float* __restrict__ zb2,
                const float* __restrict__ zw3, const float* __restrict__ zb3)
{
    extern __shared__ float sm[];
    float* in_sm  = sm;                 // 64*32   = 2048
    float* h1_sm  = sm + 2048;          // 64*132  = 8448 (row pad 132: A-frag LDS conflict-free)
    float* w2f_sm = sm + 10496;         // 8192 (w2 in tf32 B-frag order)
    float* h2_sm  = sm + 18688;         // 64*68   = 4352
    float* w3_sm  = sm + 23040;         // 64
    float* b2_sm  = sm + 23104;         // 64

    const int tid  = threadIdx.x;
    const int tile = blockIdx.x;
    const int part = blockIdx.y;
    const int g0   = tile * MK_TILE;

    const float* in = part ? z   : x;
    const float* w1 = part ? zw1 : xw1;
    const float* b1 = part ? zb1 : xb1;
    const float* w2 = part ? zw2 : xw2;
    const float* b2 = part ? zb2 : xb2;
    const float* w3 = part ? zw3 : xw3;
    const float* b3 = part ? zb3 : xb3;

    for (int idx = tid; idx < MK_TILE * 32; idx += 256)
        in_sm[idx] = in[(size_t)g0 * 32 + idx];
    // stage w2 into tf32 B-fragment order:
    // idx = (kk*8 + nt)*64 + ln*2 + hf ; k = kk*8 + (ln&3) + (hf<<2), n = nt*8 + (ln>>2)
    for (int idx = tid; idx < 8192; idx += 256) {
        int kk = idx >> 9;
        int r  = idx & 511;
        int nt = r >> 6;
        int r2 = r & 63;
        int ln = r2 >> 1, hf = r2 & 1;
        int k  = kk * 8 + (ln & 3) + (hf << 2);
        int n  = nt * 8 + (ln >> 2);
        w2f_sm[idx] = __uint_as_float(tf32_rna(w2[k * 64 + n]));
    }
    if (tid < 64) {
        w3_sm[tid] = w3[tid];
        b2_sm[tid] = b2[tid];
    }

    const int u    = tid & 127;        // hidden unit
    const int half = tid >> 7;         // sample half (0/1)

    float wc[32];
    #pragma unroll
    for (int l = 0; l < 32; ++l) wc[l] = w1[l * 128 + u];
    const float bc = b1[u];

    __syncthreads();

    // ---- phase 1 (SIMT, R14): 4 samples in flight ----
    for (int s0 = half * 32; s0 < half * 32 + 32; s0 += 4) {
        float a0 = bc, a1 = bc, a2 = bc, a3 = bc;
        const float4* r0 = (const float4*)(in_sm + (s0 + 0) * 32);
        const float4* r1 = (const float4*)(in_sm + (s0 + 1) * 32);
        const float4* r2 = (const float4*)(in_sm + (s0 + 2) * 32);
        const float4* r3 = (const float4*)(in_sm + (s0 + 3) * 32);
        #pragma unroll
        for (int l4 = 0; l4 < 8; ++l4) {
            float4 v0 = r0[l4], v1 = r1[l4], v2 = r2[l4], v3 = r3[l4];
            float w0 = wc[l4 * 4 + 0], w1c = wc[l4 * 4 + 1];
            float w2c = wc[l4 * 4 + 2], w3c = wc[l4 * 4 + 3];
            a0 = fmaf(v0.x, w0, a0); a1 = fmaf(v1.x, w0, a1);
            a2 = fmaf(v2.x, w0, a2); a3 = fmaf(v3.x, w0, a3);
            a0 = fmaf(v0.y, w1c, a0); a1 = fmaf(v1.y, w1c, a1);
            a2 = fmaf(v2.y, w1c, a2); a3 = fmaf(v3.y, w1c, a3);
            a0 = fmaf(v0.z, w2c, a0); a1 = fmaf(v1.z, w2c, a1);
            a2 = fmaf(v2.z, w2c, a2); a3 = fmaf(v3.z, w2c, a3);
            a0 = fmaf(v0.w, w3c, a0); a1 = fmaf(v1.w, w3c, a1);
            a2 = fmaf(v2.w, w3c, a2); a3 = fmaf(v3.w, w3c, a3);
        }
        h1_sm[(s0 + 0) * 132 + u] = fmaxf(a0, 0.0f);
        h1_sm[(s0 + 1) * 132 + u] = fmaxf(a1, 0.0f);
        h1_sm[(s0 + 2) * 132 + u] = fmaxf(a2, 0.0f);
        h1_sm[(s0 + 3) * 132 + u] = fmaxf(a3, 0.0f);
    }
    __syncthreads();

    // ---- phase 2 (tensor): h2 = relu(h1 @ w2 + b2) via m16n8k8 tf32 ----
    // 8 warps: m-tile = w&3 (16 rows each), n-half = w>>2 (4 n8-tiles each).
    {
        const int lane = tid & 31, wp = tid >> 5;
        const int g2 = lane >> 2, c2 = lane & 3;
        const int m  = wp & 3, nh = wp >> 2;
        const int srow = m * 16 + g2;

        float acc[4][4];
        #pragma unroll
        for (int nt = 0; nt < 4; ++nt) {
            const int n0 = nh * 32 + nt * 8 + 2 * c2;
            float bA = b2_sm[n0], bB = b2_sm[n0 + 1];
            acc[nt][0] = bA; acc[nt][1] = bB;
            acc[nt][2] = bA; acc[nt][3] = bB;
        }

        #pragma unroll 4
        for (int kk = 0; kk < 16; ++kk) {
            // A-frags (rows srow, srow+8; cols c2, c2+4 of this k8 step)
            uint32_t a0 = tf32_rna(h1_sm[srow * 132 + kk * 8 + c2]);
            uint32_t a1 = tf32_rna(h1_sm[(srow + 8) * 132 + kk * 8 + c2]);
            uint32_t a2 = tf32_rna(h1_sm[srow * 132 + kk * 8 + c2 + 4]);
            uint32_t a3 = tf32_rna(h1_sm[(srow + 8) * 132 + kk * 8 + c2 + 4]);
            #pragma unroll
            for (int nt = 0; nt < 4; ++nt) {
                uint2 bf = *(const uint2*)&w2f_sm[(size_t)(kk * 8 + nh * 4 + nt) * 64 + lane * 2];
                mma_tf32(acc[nt][0], acc[nt][1], acc[nt][2], acc[nt][3],
                         a0, a1, a2, a3, bf.x, bf.y);
            }
        }

        #pragma unroll
        for (int nt = 0; nt < 4; ++nt) {
            const int n0 = nh * 32 + nt * 8 + 2 * c2;
            h2_sm[srow * 68 + n0]           = fmaxf(acc[nt][0], 0.0f);
            h2_sm[srow * 68 + n0 + 1]       = fmaxf(acc[nt][1], 0.0f);
            h2_sm[(srow + 8) * 68 + n0]     = fmaxf(acc[nt][2], 0.0f);
            h2_sm[(srow + 8) * 68 + n0 + 1] = fmaxf(acc[nt][3], 0.0f);
        }
    }
    __syncthreads();

    // ---- phase 3 (SIMT, R14): out = h2 · w3 + b3, 4 threads/sample ----
    {
        const int s = tid >> 2, q = tid & 3;
        const float4* hr = (const float4*)(h2_sm + s * 68 + q * 16);
        const float4* wr = (const float4*)(w3_sm + q * 16);
        float acc = 0.0f;
        #pragma unroll
        for (int i = 0; i < 4; ++i) {
            float4 h = hr[i], w = wr[i];
            acc = fmaf(h.x, w.x, acc);
            acc = fmaf(h.y, w.y, acc);
            acc = fmaf(h.z, w.z, acc);
            acc = fmaf(h.w, w.w, acc);
        }
        acc += __shfl_xor_sync(0xffffffffu, acc, 1);
        acc += __shfl_xor_sync(0xffffffffu, acc, 2);
        if (q == 0)
            g_partial[(PK_NCHUNK + part) * BATCH + g0 + s] = acc + b3[0];
    }

    // ---- arrival + (maybe) fused final reduction ----
    {
        __shared__ int last;
        const int pt = tile >> 2;            // 256-sample tile index
        __threadfence();
        __syncthreads();
        if (tid == 0)
            last = (atomicAdd(&g_cnt[pt], 1) == ARRIVALS - 1) ? 1 : 0;
        __syncthreads();
        if (last) {
            __threadfence();
            const int base = pt * 256;
            out[base + tid] = reduce_sample(base + tid);
            __syncthreads();
            if (tid == 0) g_cnt[pt] = 0;     // reset for next graph replay
        }
    }
}

// ---------------------------------------------------------------------------
// Kernel 2: structured interaction + per-pair MLPs via tf32 mma, pairs-outer.
// grid = (32 sample tiles of 256, 32 chunks) = 1024 CTAs, 128 threads.
// R9 loop body (proven best) + fused-reduction arrival epilogue. (R14 verbatim)
// ---------------------------------------------------------------------------
__global__ __launch_bounds__(128, 6)
void pair_kernel(float* __restrict__ out,
                 const float* __restrict__ xzw, const float* __restrict__ xzb,
                 const float* __restrict__ pw1, const float* __restrict__ pb1,
                 const float* __restrict__ pw2)
{
    __shared__ __align__(16) ull   x2_sm[256];         // dup-packed x column (2KB)
    __shared__ __align__(16) float wq_sm[1024];        // [pair][c]{wx_c,wx_c4,wz_c,wz_c4,bb_c,bb_c4,0,0}
    __shared__ __align__(16) float bf_sm[4096];        // pw1 tf32 B-frags
    __shared__ __align__(16) float ep_sm[1024];        // [pair][cp]{pb,pb,pw2,pw2}

    const int tid   = threadIdx.x;
    const int tile  = blockIdx.x;    // 0..31
    const int chunk = blockIdx.y;    // 0..31
    const int g0    = tile * 256;
    const int p0    = chunk * 32;

    // ---- staging ----
    for (int idx = tid; idx < 256; idx += 128) {
        float xv = g_xT[(size_t)chunk * BATCH + g0 + idx];
        x2_sm[idx] = pack2(xv, xv);
    }
    for (int idx = tid; idx < 1024; idx += 128) {
        int pr = idx >> 5, c = (idx >> 3) & 3, e = idx & 7;
        int p  = p0 + pr;
        int j  = c + ((e & 1) << 2);
        float v = 0.f;
        if (e < 2)      v = xzw[(size_t)chunk * OUT_U + p * 8 + j];
        else if (e < 4) v = xzw[(size_t)(32 + pr) * OUT_U + p * 8 + j];
        else if (e < 6) v = xzb[p * 8 + j];
        wq_sm[idx] = v;
    }
    for (int idx = tid; idx < 4096; idx += 128) {
        int pr = idx >> 7, r = idx & 127;
        int nm = r >> 6, r2 = r & 63;
        int ln = r2 >> 1, half = r2 & 1;
        int k = (ln & 3) + (half << 2);
        int n = (ln >> 2) + (nm << 3);
        bf_sm[idx] = __uint_as_float(tf32_rna(pw1[(size_t)(p0 + pr) * 128 + k * 16 + n]));
    }
    for (int idx = tid; idx < 1024; idx += 128) {
        int pr = idx >> 5, r = idx & 31;
        int cp = r >> 2, e = r & 3;
        int col = 2 * cp + (e & 1);
        ep_sm[idx] = (e < 2) ? pb1[(p0 + pr) * 16 + col]
                             : pw2[(p0 + pr) * 16 + col];
    }
    __syncthreads();

    const int lane = tid & 31, w = tid >> 5;   // w 0..3
    const int g = lane >> 2, c = lane & 3;
    const int sbase = w * 64;                  // warp's sample base within tile

    float outv[8];
    #pragma unroll
    for (int i = 0; i < 8; ++i) outv[i] = 0.f;

    const float* zT = g_zT + g0;

    #pragma unroll 1
    for (int pl = 0; pl < 32; ++pl) {
        // per-pair registers (reused across 4 subtiles)
        ulonglong2 wu = *(const ulonglong2*)&wq_sm[(pl * 4 + c) * 8];
        ull bbu = *(const ull*)&wq_sm[(pl * 4 + c) * 8 + 4];
        uint2 bf0 = *(const uint2*)&bf_sm[pl * 128 + lane * 2];
        uint2 bf1 = *(const uint2*)&bf_sm[pl * 128 + 64 + lane * 2];
        float4 e0 = *(const float4*)&ep_sm[(pl * 8 + c) * 4];
        float4 e1 = *(const float4*)&ep_sm[(pl * 8 + c + 4) * 4];
        const float* zcol = zT + (size_t)pl * BATCH;

        #pragma unroll
        for (int sub = 0; sub < 4; ++sub) {
            const int srow = sbase + sub * 16 + g;
            float zg  = zcol[srow];
            float zg8 = zcol[srow + 8];

            // h in A-frag layout: rows {g, g+8} x cols {c, c+4}
            ull hg  = fma2(wu.x, x2_sm[srow],     fma2(wu.y, pack2(zg,  zg),  bbu));
            ull hg8 = fma2(wu.x, x2_sm[srow + 8], fma2(wu.y, pack2(zg8, zg8), bbu));
            float h0, h2, h1, h3;
            unpack2(hg,  h0, h2);
            unpack2(hg8, h1, h3);
            // raw fp32 bits: tf32 shares fp32 layout; MMA ignores low mantissa
            uint32_t a0 = __float_as_uint(fmaxf(h0, 0.f));
            uint32_t a1 = __float_as_uint(fmaxf(h1, 0.f));
            uint32_t a2 = __float_as_uint(fmaxf(h2, 0.f));
            uint32_t a3 = __float_as_uint(fmaxf(h3, 0.f));

            // t = h @ pw1 + pb1
            float d0 = e0.x, d1 = e0.y, d2 = e0.x, d3 = e0.y;
            mma_tf32(d0, d1, d2, d3, a0, a1, a2, a3, bf0.x, bf0.y);
            float f0 = e1.x, f1 = e1.y, f2 = e1.x, f3 = e1.y;
            mma_tf32(f0, f1, f2, f3, a0, a1, a2, a3, bf1.x, bf1.y);

            // out += relu(t) . pw2
            outv[2*sub]   = fmaf(fmaxf(d0, 0.f), e0.z, outv[2*sub]);
            outv[2*sub]   = fmaf(fmaxf(d1, 0.f), e0.w, outv[2*sub]);
            outv[2*sub]   = fmaf(fmaxf(f0, 0.f), e1.z, outv[2*sub]);
            outv[2*sub]   = fmaf(fmaxf(f1, 0.f), e1.w, outv[2*sub]);
            outv[2*sub+1] = fmaf(fmaxf(d2, 0.f), e0.z, outv[2*sub+1]);
            outv[2*sub+1] = fmaf(fmaxf(d3, 0.f), e0.w, outv[2*sub+1]);
            outv[2*sub+1] = fmaf(fmaxf(f2, 0.f), e1.z, outv[2*sub+1]);
            outv[2*sub+1] = fmaf(fmaxf(f3, 0.f), e1.w, outv[2*sub+1]);
        }
    }

    // reduce over the 4 col-partition threads of each row group
    #pragma unroll
    for (int i = 0; i < 8; ++i) {
        outv[i] += __shfl_xor_sync(0xffffffffu, outv[i], 1);
        outv[i] += __shfl_xor_sync(0xffffffffu, outv[i], 2);
    }
    if (c == 0) {
        #pragma unroll
        for (int sub = 0; sub < 4; ++sub) {
            g_partial[(size_t)chunk * BATCH + g0 + sbase + sub * 16 + g]     = outv[2*sub];
            g_partial[(size_t)chunk * BATCH + g0 + sbase + sub * 16 + g + 8] = outv[2*sub + 1];
        }
    }

    // ---- arrival + (maybe) fused final reduction ----
    {
        __shared__ int last;
        __threadfence();
        __syncthreads();
        if (tid == 0)
            last = (atomicAdd(&g_cnt[tile], 1) == ARRIVALS - 1) ? 1 : 0;
        __syncthreads();
        if (last) {
            __threadfence();
            for (int s = tid; s < 256; s += 128)
                out[g0 + s] = reduce_sample(g0 + s);
            __syncthreads();
            if (tid == 0) g_cnt[tile] = 0;   // reset for next graph replay
        }
    }
}

// ---------------------------------------------------------------------------
extern "C" void kernel_launch(void* const* d_in, const int* in_sizes, int n_in,
                              void* d_out, int out_size)
{
    const float* x   = (const float*)d_in[0];
    const float* z   = (const float*)d_in[1];
    const float* xw1 = (const float*)d_in[2];
    const float* xb1 = (const float*)d_in[3];
    const float* xw2 = (const float*)d_in[4];
    const float* xb2 = (const float*)d_in[5];
    const float* xw3 = (const float*)d_in[6];
    const float* xb3 = (const float*)d_in[7];
    const float* zw1 = (const float*)d_in[8];
    const float* zb1 = (const float*)d_in[9];
    const float* zw2 = (const float*)d_in[10];
    const float* zb2 = (const float*)d_in[11];
    const float* zw3 = (const float*)d_in[12];
    const float* zb3 = (const float*)d_in[13];
    const float* xzw = (const float*)d_in[14];
    const float* xzb = (const float*)d_in[15];
    const float* pw1 = (const float*)d_in[16];
    const float* pb1 = (const float*)d_in[17];
    const float* pw2 = (const float*)d_in[18];
    float* out = (float*)d_out;

    static cudaStream_t s2 = nullptr;
    static cudaEvent_t  e_fork = nullptr, e_join = nullptr;
    if (s2 == nullptr) {
        cudaStreamCreateWithFlags(&s2, cudaStreamNonBlocking);
        cudaEventCreateWithFlags(&e_fork, cudaEventDisableTiming);
        cudaEventCreateWithFlags(&e_join, cudaEventDisableTiming);
        cudaFuncSetAttribute(pair_kernel,
            cudaFuncAttributePreferredSharedMemoryCarveout, 100);
    }

    const size_t smem_mlp = 23168u * sizeof(float);   // 92672 B
    cudaFuncSetAttribute(mlp_kernel, cudaFuncAttributeMaxDynamicSharedMemorySize, (int)smem_mlp);

    // fork: mlp on side stream (its CTAs also feed the fused reduction)
    cudaEventRecord(e_fork, 0);
    cudaStreamWaitEvent(s2, e_fork, 0);
    mlp_kernel<<<dim3(MK_NTILE, 2), 256, smem_mlp, s2>>>(out, x, z,
        xw1, xb1, xw2, xb2, xw3, xb3,
        zw1, zb1, zw2, zb2, zw3, zb3);
    cudaEventRecord(e_join, s2);

    transpose_kernel<<<BATCH / 64, 256>>>(x, z);
    pair_kernel<<<dim3(32, 32), 128>>>(out, xzw, xzb, pw1, pb1, pw2);

    // join side stream so the captured graph's completion covers mlp's writes
    cudaStreamWaitEvent(0, e_join, 0);
}